// round 1
// baseline (speedup 1.0000x reference)
#include <cuda_runtime.h>
#include <cstdint>
#include <cstddef>

// Problem constants
#define BB    4
#define NN    4096
#define DIN   256
#define DOUT  128
#define COS_EPS    0.001f
#define THRESHOLD  0.1f
#define LEAKY      0.01f

// Scratch (no allocations allowed)
__device__ float g_h[BB * NN * DOUT];      // 8 MB: leaky_relu(z @ W)
__device__ float g_norm[BB * NN];          // row L2 norms

// ---------------------------------------------------------------------------
// Kernel A: h = leaky_relu(z @ W).  z: [16384, 256], W: [256, 128].
// Tile: 128 rows x 128 cols, K chunks of 64. 256 threads, 8x8 per thread.
// Smem layout: Zs transposed [k][m] (rowlen 132), Ws natural [k][n] (rowlen 128).
// ---------------------------------------------------------------------------
#define Z_ROWLEN 132
__global__ void __launch_bounds__(256, 1)
gemm1_kernel(const float* __restrict__ z, const float* __restrict__ W)
{
    extern __shared__ float smem[];
    float* Zs = smem;                       // [64][132]
    float* Ws = smem + 64 * Z_ROWLEN;       // [64][128]

    const int m0  = blockIdx.x * 128;
    const int tid = threadIdx.x;
    const int tm  = tid >> 4;               // 0..15
    const int tn  = tid & 15;               // 0..15

    float acc[8][8];
#pragma unroll
    for (int i = 0; i < 8; i++)
#pragma unroll
        for (int j = 0; j < 8; j++) acc[i][j] = 0.f;

    for (int k0 = 0; k0 < DIN; k0 += 64) {
        // Load Z chunk: 128 rows x 64 k  (2048 float4, 8 per thread), transpose to [k][m]
#pragma unroll
        for (int t = 0; t < 8; t++) {
            int idx = tid + t * 256;        // 0..2047
            int r   = idx >> 4;             // row 0..127
            int kk  = (idx & 15) << 2;      // k offset 0..60
            float4 v = *(const float4*)(z + (size_t)(m0 + r) * DIN + k0 + kk);
            Zs[(kk + 0) * Z_ROWLEN + r] = v.x;
            Zs[(kk + 1) * Z_ROWLEN + r] = v.y;
            Zs[(kk + 2) * Z_ROWLEN + r] = v.z;
            Zs[(kk + 3) * Z_ROWLEN + r] = v.w;
        }
        // Load W chunk: 64 k-rows x 128 cols, natural layout
#pragma unroll
        for (int t = 0; t < 8; t++) {
            int idx = tid + t * 256;        // 0..2047 float4
            int kk  = idx >> 5;             // 0..63
            int n4  = (idx & 31) << 2;      // 0..124
            float4 v = *(const float4*)(W + (size_t)(k0 + kk) * DOUT + n4);
            *(float4*)&Ws[kk * DOUT + n4] = v;
        }
        __syncthreads();

#pragma unroll 8
        for (int k = 0; k < 64; k++) {
            float a[8], b[8];
            *(float4*)(a)     = *(float4*)&Zs[k * Z_ROWLEN + tm * 8];
            *(float4*)(a + 4) = *(float4*)&Zs[k * Z_ROWLEN + tm * 8 + 4];
            *(float4*)(b)     = *(float4*)&Ws[k * DOUT + tn * 8];
            *(float4*)(b + 4) = *(float4*)&Ws[k * DOUT + tn * 8 + 4];
#pragma unroll
            for (int i = 0; i < 8; i++)
#pragma unroll
                for (int j = 0; j < 8; j++)
                    acc[i][j] += a[i] * b[j];
        }
        __syncthreads();
    }

    // Epilogue: leaky relu, store h
#pragma unroll
    for (int i = 0; i < 8; i++) {
        int row = m0 + tm * 8 + i;
        float v[8];
#pragma unroll
        for (int j = 0; j < 8; j++) {
            float x = acc[i][j];
            v[j] = (x > 0.f) ? x : LEAKY * x;
        }
        float* dst = g_h + (size_t)row * DOUT + tn * 8;
        *(float4*)(dst)     = make_float4(v[0], v[1], v[2], v[3]);
        *(float4*)(dst + 4) = make_float4(v[4], v[5], v[6], v[7]);
    }
}

// ---------------------------------------------------------------------------
// Kernel B: row L2 norms of h. One warp per row.
// ---------------------------------------------------------------------------
__global__ void __launch_bounds__(256)
norm_kernel()
{
    int gwarp = (blockIdx.x * blockDim.x + threadIdx.x) >> 5;
    int lane  = threadIdx.x & 31;
    if (gwarp >= BB * NN) return;
    const float* hr = g_h + (size_t)gwarp * DOUT;
    float s = 0.f;
#pragma unroll
    for (int c = 0; c < 4; c++) {
        float x = hr[lane + c * 32];
        s += x * x;
    }
#pragma unroll
    for (int off = 16; off > 0; off >>= 1)
        s += __shfl_xor_sync(0xFFFFFFFFu, s, off);
    if (lane == 0) g_norm[gwarp] = sqrtf(s);
}

// ---------------------------------------------------------------------------
// Kernel C: per-batch Gram + cosine + threshold, symmetric (bx <= by).
// C[b] = thr(|H H^T / max(n_i n_j, eps)|).  Tile 128x128, K=128 smem-resident.
// Smem: As, Bs transposed [k][localrow], rowlen 132.
// ---------------------------------------------------------------------------
#define G_ROWLEN 132
__global__ void __launch_bounds__(256, 1)
gram_kernel(float* __restrict__ out)
{
    const int bx = blockIdx.x;     // row-tile
    const int by = blockIdx.y;     // col-tile
    const int b  = blockIdx.z;
    if (by < bx) return;

    extern __shared__ float smem[];
    float* As = smem;                        // [128][132]
    float* Bs = smem + 128 * G_ROWLEN;       // [128][132]

    const int tid = threadIdx.x;
    const int tm  = tid >> 4;
    const int tn  = tid & 15;
    const int i0  = bx * 128;
    const int j0  = by * 128;
    const size_t hbase = (size_t)b * NN * DOUT;

    // Load both 128x128 tiles (transposed into [k][m]); 16 float4 each / thread
#pragma unroll
    for (int t = 0; t < 16; t++) {
        int idx = tid + t * 256;             // 0..4095 float4 index
        int r   = idx >> 5;                  // 0..127
        int kk  = (idx & 31) << 2;           // 0..124
        float4 va = *(const float4*)(g_h + hbase + (size_t)(i0 + r) * DOUT + kk);
        As[(kk + 0) * G_ROWLEN + r] = va.x;
        As[(kk + 1) * G_ROWLEN + r] = va.y;
        As[(kk + 2) * G_ROWLEN + r] = va.z;
        As[(kk + 3) * G_ROWLEN + r] = va.w;
        float4 vb = *(const float4*)(g_h + hbase + (size_t)(j0 + r) * DOUT + kk);
        Bs[(kk + 0) * G_ROWLEN + r] = vb.x;
        Bs[(kk + 1) * G_ROWLEN + r] = vb.y;
        Bs[(kk + 2) * G_ROWLEN + r] = vb.z;
        Bs[(kk + 3) * G_ROWLEN + r] = vb.w;
    }
    __syncthreads();

    float acc[8][8];
#pragma unroll
    for (int i = 0; i < 8; i++)
#pragma unroll
        for (int j = 0; j < 8; j++) acc[i][j] = 0.f;

#pragma unroll 8
    for (int k = 0; k < 128; k++) {
        float a[8], bvals[8];
        *(float4*)(a)         = *(float4*)&As[k * G_ROWLEN + tm * 8];
        *(float4*)(a + 4)     = *(float4*)&As[k * G_ROWLEN + tm * 8 + 4];
        *(float4*)(bvals)     = *(float4*)&Bs[k * G_ROWLEN + tn * 8];
        *(float4*)(bvals + 4) = *(float4*)&Bs[k * G_ROWLEN + tn * 8 + 4];
#pragma unroll
        for (int i = 0; i < 8; i++)
#pragma unroll
            for (int j = 0; j < 8; j++)
                acc[i][j] += a[i] * bvals[j];
    }

    // Epilogue: cosine + abs + threshold (in place)
    const size_t nbase = (size_t)b * NN;
    float nm[8], nn2[8];
#pragma unroll
    for (int i = 0; i < 8; i++) nm[i]  = g_norm[nbase + i0 + tm * 8 + i];
#pragma unroll
    for (int j = 0; j < 8; j++) nn2[j] = g_norm[nbase + j0 + tn * 8 + j];

#pragma unroll
    for (int i = 0; i < 8; i++)
#pragma unroll
        for (int j = 0; j < 8; j++) {
            float d = fmaxf(nm[i] * nn2[j], COS_EPS);
            float v = fabsf(acc[i][j]) / d;
            acc[i][j] = (v > THRESHOLD) ? v : 0.f;
        }

    float* outb = out + (size_t)b * NN * NN;

    // Main tile (coalesced float4 along columns)
#pragma unroll
    for (int i = 0; i < 8; i++) {
        size_t row = (size_t)(i0 + tm * 8 + i);
        float* dst = outb + row * NN + (j0 + tn * 8);
        *(float4*)(dst)     = make_float4(acc[i][0], acc[i][1], acc[i][2], acc[i][3]);
        *(float4*)(dst + 4) = make_float4(acc[i][4], acc[i][5], acc[i][6], acc[i][7]);
    }

    // Mirror tile (float4 along rows of the mirror = along m)
    if (bx != by) {
#pragma unroll
        for (int j = 0; j < 8; j++) {
            size_t col = (size_t)(j0 + tn * 8 + j);
            float* dst = outb + col * NN + (i0 + tm * 8);
            *(float4*)(dst)     = make_float4(acc[0][j], acc[1][j], acc[2][j], acc[3][j]);
            *(float4*)(dst + 4) = make_float4(acc[4][j], acc[5][j], acc[6][j], acc[7][j]);
        }
    }
}

// ---------------------------------------------------------------------------
extern "C" void kernel_launch(void* const* d_in, const int* in_sizes, int n_in,
                              void* d_out, int out_size)
{
    (void)in_sizes; (void)n_in; (void)out_size;
    const float* z = (const float*)d_in[0];   // [4, 4096, 256]
    const float* W = (const float*)d_in[1];   // [256, 128]
    float* out = (float*)d_out;               // [4, 4096, 4096]

    const int smem1 = (64 * Z_ROWLEN + 64 * DOUT) * sizeof(float);   // ~66.5 KB
    const int smemG = 2 * 128 * G_ROWLEN * sizeof(float);            // ~135 KB

    static bool attrs_set = false;
    if (!attrs_set) {
        cudaFuncSetAttribute(gemm1_kernel, cudaFuncAttributeMaxDynamicSharedMemorySize, smem1);
        cudaFuncSetAttribute(gram_kernel,  cudaFuncAttributeMaxDynamicSharedMemorySize, smemG);
        attrs_set = true;
    }

    // A: h = leaky_relu(z @ W)
    gemm1_kernel<<<BB * NN / 128, 256, smem1>>>(z, W);
    // B: row norms
    norm_kernel<<<(BB * NN) / 8, 256>>>();
    // C: symmetric Gram + cosine + threshold
    dim3 grid(NN / 128, NN / 128, BB);
    gram_kernel<<<grid, 256, smemG>>>(out);
}

// round 5
// speedup vs baseline: 1.6555x; 1.6555x over previous
#include <cuda_runtime.h>
#include <cuda_bf16.h>
#include <cstdint>
#include <cstddef>

// Problem constants
#define BB    4
#define NN    4096
#define DIN   256
#define DOUT  128
#define COS_EPS    0.001f
#define THRESHOLD  0.1f
#define LEAKY      0.01f
#define FIX_WIN    2e-4f
#define MAXFIX     (1u << 22)

// ---------------------------------------------------------------------------
// Scratch (static device globals; no allocations allowed)
// ---------------------------------------------------------------------------
__device__ float          g_h[BB * NN * DOUT];       // fp32 h (for fixup + norms)
__device__ __nv_bfloat16  g_hi[BB * NN * DOUT];      // bf16 high part
__device__ __nv_bfloat16  g_lo[BB * NN * DOUT];      // bf16 low part
__device__ float          g_norm[BB * NN];
__device__ float          g_rnorm[BB * NN];
__device__ unsigned int   g_fix_cnt;
__device__ unsigned int   g_fix[MAXFIX];

__device__ __forceinline__ uint32_t smem_u32(const void* p) {
    uint32_t a;
    asm("{ .reg .u64 t; cvta.to.shared.u64 t, %1; cvt.u32.u64 %0, t; }"
        : "=r"(a) : "l"(p));
    return a;
}

__device__ __forceinline__ void ldsm_x4(uint32_t* r, uint32_t addr) {
    asm volatile("ldmatrix.sync.aligned.m8n8.x4.shared.b16 {%0,%1,%2,%3}, [%4];"
                 : "=r"(r[0]), "=r"(r[1]), "=r"(r[2]), "=r"(r[3]) : "r"(addr));
}
__device__ __forceinline__ void mma_bf16(float* d, const uint32_t* a, const uint32_t* b) {
    asm volatile(
        "mma.sync.aligned.m16n8k16.row.col.f32.bf16.bf16.f32 "
        "{%0,%1,%2,%3}, {%4,%5,%6,%7}, {%8,%9}, {%0,%1,%2,%3};"
        : "+f"(d[0]), "+f"(d[1]), "+f"(d[2]), "+f"(d[3])
        : "r"(a[0]), "r"(a[1]), "r"(a[2]), "r"(a[3]), "r"(b[0]), "r"(b[1]));
}

// Single extern shared symbol for the whole TU
extern __shared__ char smem_raw[];

// ---------------------------------------------------------------------------
// Kernel A: h = leaky_relu(z @ W), fp32 SIMT
// ---------------------------------------------------------------------------
#define Z_ROWLEN 132
__global__ void __launch_bounds__(256, 1)
gemm1_kernel(const float* __restrict__ z, const float* __restrict__ W)
{
    float* smem = (float*)smem_raw;
    float* Zs = smem;
    float* Ws = smem + 64 * Z_ROWLEN;

    const int m0  = blockIdx.x * 128;
    const int tid = threadIdx.x;
    const int tm  = tid >> 4;
    const int tn  = tid & 15;

    float acc[8][8];
#pragma unroll
    for (int i = 0; i < 8; i++)
#pragma unroll
        for (int j = 0; j < 8; j++) acc[i][j] = 0.f;

    for (int k0 = 0; k0 < DIN; k0 += 64) {
#pragma unroll
        for (int t = 0; t < 8; t++) {
            int idx = tid + t * 256;
            int r   = idx >> 4;
            int kk  = (idx & 15) << 2;
            float4 v = *(const float4*)(z + (size_t)(m0 + r) * DIN + k0 + kk);
            Zs[(kk + 0) * Z_ROWLEN + r] = v.x;
            Zs[(kk + 1) * Z_ROWLEN + r] = v.y;
            Zs[(kk + 2) * Z_ROWLEN + r] = v.z;
            Zs[(kk + 3) * Z_ROWLEN + r] = v.w;
        }
#pragma unroll
        for (int t = 0; t < 8; t++) {
            int idx = tid + t * 256;
            int kk  = idx >> 5;
            int n4  = (idx & 31) << 2;
            float4 v = *(const float4*)(W + (size_t)(k0 + kk) * DOUT + n4);
            *(float4*)&Ws[kk * DOUT + n4] = v;
        }
        __syncthreads();

#pragma unroll 8
        for (int k = 0; k < 64; k++) {
            float a[8], b[8];
            *(float4*)(a)     = *(float4*)&Zs[k * Z_ROWLEN + tm * 8];
            *(float4*)(a + 4) = *(float4*)&Zs[k * Z_ROWLEN + tm * 8 + 4];
            *(float4*)(b)     = *(float4*)&Ws[k * DOUT + tn * 8];
            *(float4*)(b + 4) = *(float4*)&Ws[k * DOUT + tn * 8 + 4];
#pragma unroll
            for (int i = 0; i < 8; i++)
#pragma unroll
                for (int j = 0; j < 8; j++)
                    acc[i][j] += a[i] * b[j];
        }
        __syncthreads();
    }

#pragma unroll
    for (int i = 0; i < 8; i++) {
        int row = m0 + tm * 8 + i;
        float v[8];
#pragma unroll
        for (int j = 0; j < 8; j++) {
            float x = acc[i][j];
            v[j] = (x > 0.f) ? x : LEAKY * x;
        }
        float* dst = g_h + (size_t)row * DOUT + tn * 8;
        *(float4*)(dst)     = make_float4(v[0], v[1], v[2], v[3]);
        *(float4*)(dst + 4) = make_float4(v[4], v[5], v[6], v[7]);
    }
}

// ---------------------------------------------------------------------------
// Kernel B: per row — norm, rnorm, bf16 hi/lo split. One warp per row.
// ---------------------------------------------------------------------------
__global__ void __launch_bounds__(256)
split_kernel()
{
    int row  = blockIdx.x * 8 + (threadIdx.x >> 5);
    int lane = threadIdx.x & 31;
    const float* hr = g_h + (size_t)row * DOUT;

    float4 x = ((const float4*)hr)[lane];
    float s = x.x * x.x + x.y * x.y + x.z * x.z + x.w * x.w;
#pragma unroll
    for (int off = 16; off > 0; off >>= 1)
        s += __shfl_xor_sync(0xFFFFFFFFu, s, off);

    __nv_bfloat16 h0 = __float2bfloat16(x.x);
    __nv_bfloat16 h1 = __float2bfloat16(x.y);
    __nv_bfloat16 h2 = __float2bfloat16(x.z);
    __nv_bfloat16 h3 = __float2bfloat16(x.w);
    __nv_bfloat16 l0 = __float2bfloat16(x.x - __bfloat162float(h0));
    __nv_bfloat16 l1 = __float2bfloat16(x.y - __bfloat162float(h1));
    __nv_bfloat16 l2 = __float2bfloat16(x.z - __bfloat162float(h2));
    __nv_bfloat16 l3 = __float2bfloat16(x.w - __bfloat162float(h3));

    __nv_bfloat162 hp0 = __nv_bfloat162(h0, h1), hp1 = __nv_bfloat162(h2, h3);
    __nv_bfloat162 lp0 = __nv_bfloat162(l0, l1), lp1 = __nv_bfloat162(l2, l3);

    uint2 hv, lv;
    hv.x = *(uint32_t*)&hp0; hv.y = *(uint32_t*)&hp1;
    lv.x = *(uint32_t*)&lp0; lv.y = *(uint32_t*)&lp1;
    ((uint2*)(g_hi + (size_t)row * DOUT))[lane] = hv;
    ((uint2*)(g_lo + (size_t)row * DOUT))[lane] = lv;

    if (lane == 0) {
        float n = sqrtf(s);
        g_norm[row]  = n;
        g_rnorm[row] = 1.0f / n;
    }
}

__global__ void reset_kernel() { g_fix_cnt = 0; }

// ---------------------------------------------------------------------------
// Kernel C: mma.sync bf16x3 Gram + cosine + threshold, symmetric tiles.
// 128x128 tile, 8 warps (4m x 2n), warp tile 32x64, K=128 smem-resident.
// Smem tiles: row-major [128 rows][128 bf16 = 256B], 16B chunks XOR-swizzled:
//   off(row, chunk) = row*256 + ((chunk ^ (row&7)) << 4)
// B operand: non-trans ldmatrix over n-rows gives thread l -> (n=l/4,
// k=2*(l%4)+{0,1}) == exact m16n8k16 col-major B fragment for C = A*B^T.
// ---------------------------------------------------------------------------
#define OFF_A_HI    0
#define OFF_A_LO    32768
#define OFF_B_HI    65536
#define OFF_B_LO    98304
#define OFF_NA      131072
#define OFF_NB      (OFF_NA + 512)
#define OFF_RNA     (OFF_NB + 512)
#define OFF_RNB     (OFF_RNA + 512)
#define GRAM_SMEM   (OFF_RNB + 512)
#define OFF_STAGE   0              /* reuse operand smem after MMA */
#define STAGE_LD    129

__global__ void __launch_bounds__(256, 1)
gram_mma_kernel(float* __restrict__ out)
{
    const int bx = blockIdx.x, by = blockIdx.y, b = blockIdx.z;
    if (by < bx) return;

    char* smem = smem_raw;
    const uint32_t sb = smem_u32(smem);
    const int tid  = threadIdx.x;
    const int wid  = tid >> 5;
    const int lane = tid & 31;
    const int warp_m = wid >> 1;          // 0..3
    const int warp_n = wid & 1;           // 0..1

    const int i0 = bx * 128, j0 = by * 128;
    const size_t hbase = (size_t)b * NN * DOUT;
    const size_t nbase = (size_t)b * NN;

    // ---- Load operand tiles (hi/lo for A-rows and B-rows), swizzled ----
    {
        const uint4* srcA_hi = (const uint4*)(g_hi + hbase + (size_t)i0 * DOUT);
        const uint4* srcA_lo = (const uint4*)(g_lo + hbase + (size_t)i0 * DOUT);
        const uint4* srcB_hi = (const uint4*)(g_hi + hbase + (size_t)j0 * DOUT);
        const uint4* srcB_lo = (const uint4*)(g_lo + hbase + (size_t)j0 * DOUT);
#pragma unroll
        for (int t = 0; t < 8; t++) {
            int idx = tid + t * 256;            // 0..2047 uint4 (one per 16B chunk)
            int row = idx >> 4;                 // 16 chunks per 256B row
            int c   = idx & 15;
            uint32_t off = (uint32_t)(row * 256) + (uint32_t)((c ^ (row & 7)) << 4);
            *(uint4*)(smem + OFF_A_HI + off) = srcA_hi[idx];
            *(uint4*)(smem + OFF_A_LO + off) = srcA_lo[idx];
            *(uint4*)(smem + OFF_B_HI + off) = srcB_hi[idx];
            *(uint4*)(smem + OFF_B_LO + off) = srcB_lo[idx];
        }
        if (tid < 128) {
            ((float*)(smem + OFF_NA))[tid]  = g_norm[nbase + i0 + tid];
            ((float*)(smem + OFF_NB))[tid]  = g_norm[nbase + j0 + tid];
            ((float*)(smem + OFF_RNA))[tid] = g_rnorm[nbase + i0 + tid];
            ((float*)(smem + OFF_RNB))[tid] = g_rnorm[nbase + j0 + tid];
        }
    }
    __syncthreads();

    // ---- MMA mainloop: 3 passes (hi*hi, hi*lo, lo*hi), 8 ksteps of 16 ----
    float acc[2][8][4];
#pragma unroll
    for (int mf = 0; mf < 2; mf++)
#pragma unroll
        for (int nf = 0; nf < 8; nf++)
#pragma unroll
            for (int r = 0; r < 4; r++) acc[mf][nf][r] = 0.f;

    const uint32_t aoffs[3] = { sb + OFF_A_HI, sb + OFF_A_HI, sb + OFF_A_LO };
    const uint32_t boffs[3] = { sb + OFF_B_HI, sb + OFF_B_LO, sb + OFF_B_HI };

    // Lane-dependent address pieces:
    // A x4: lanes 0-15 rows (m), k-chunk lo; lanes 16-31 same rows, k-chunk hi
    const int a_row_lo = warp_m * 32 + (lane & 15);      // + mf*16
    const int a_ksel   = lane >> 4;
    // B x4 (non-trans): lanes 0-7 n0-7/k-lo, 8-15 n0-7/k-hi,
    //                   16-23 n8-15/k-lo, 24-31 n8-15/k-hi
    const int b_row_lo = warp_n * 64 + (lane & 7) + ((lane >> 4) << 3);  // + q*16
    const int b_ksel   = (lane >> 3) & 1;

#pragma unroll
    for (int p = 0; p < 3; p++) {
        const uint32_t abase = aoffs[p];
        const uint32_t bbase = boffs[p];
#pragma unroll
        for (int ks = 0; ks < 8; ks++) {
            uint32_t a[2][4];
#pragma unroll
            for (int mf = 0; mf < 2; mf++) {
                int row = a_row_lo + mf * 16;
                uint32_t addr = abase + row * 256 +
                                (uint32_t)((((ks * 2 + a_ksel) ^ (row & 7))) << 4);
                ldsm_x4(a[mf], addr);
            }
            uint32_t bfr[4][4];
#pragma unroll
            for (int q = 0; q < 4; q++) {
                int row = b_row_lo + q * 16;
                uint32_t addr = bbase + row * 256 +
                                (uint32_t)((((ks * 2 + b_ksel) ^ (row & 7))) << 4);
                ldsm_x4(bfr[q], addr);   // non-trans: correct B^T fragment
            }
#pragma unroll
            for (int mf = 0; mf < 2; mf++)
#pragma unroll
                for (int q = 0; q < 4; q++) {
                    mma_bf16(acc[mf][q * 2 + 0], a[mf], &bfr[q][0]);
                    mma_bf16(acc[mf][q * 2 + 1], a[mf], &bfr[q][2]);
                }
        }
    }
    __syncthreads();   // all operand reads done before stage overwrite

    // ---- Epilogue: cosine + abs + threshold + fixup flag, into staging ----
    {
        const float* nA  = (const float*)(smem + OFF_NA);
        const float* nB  = (const float*)(smem + OFF_NB);
        const float* rnA = (const float*)(smem + OFF_RNA);
        const float* rnB = (const float*)(smem + OFF_RNB);
        float* stage = (float*)(smem + OFF_STAGE);

#pragma unroll
        for (int mf = 0; mf < 2; mf++) {
            int r_lo = warp_m * 32 + mf * 16 + (lane >> 2);
#pragma unroll
            for (int half = 0; half < 2; half++) {
                int r = r_lo + half * 8;
                float nm = nA[r], rnm = rnA[r];
#pragma unroll
                for (int nf = 0; nf < 8; nf++) {
                    int c0 = warp_n * 64 + nf * 8 + (lane & 3) * 2;
#pragma unroll
                    for (int e = 0; e < 2; e++) {
                        int c = c0 + e;
                        float dot = acc[mf][nf][half * 2 + e];
                        float t = nm * nB[c];
                        float f = (t >= COS_EPS) ? (rnm * rnB[c]) : (1.0f / COS_EPS);
                        float v = fabsf(dot) * f;
                        if (fabsf(v - THRESHOLD) < FIX_WIN) {
                            unsigned idx = atomicAdd(&g_fix_cnt, 1u);
                            if (idx < MAXFIX)
                                g_fix[idx] = ((unsigned)b << 24) |
                                             ((unsigned)(i0 + r) << 12) |
                                             (unsigned)(j0 + c);
                        }
                        stage[r * STAGE_LD + c] = (v > THRESHOLD) ? v : 0.f;
                    }
                }
            }
        }
    }
    __syncthreads();

    // ---- Coalesced stores: main tile + mirror ----
    {
        const float* stage = (const float*)(smem + OFF_STAGE);
        float* outb = out + (size_t)b * NN * NN;
#pragma unroll
        for (int t = 0; t < 64; t++) {
            int idx = tid + t * 256;
            int r = idx >> 7, c = idx & 127;
            outb[(size_t)(i0 + r) * NN + (j0 + c)] = stage[r * STAGE_LD + c];
        }
        if (bx != by) {
#pragma unroll
            for (int t = 0; t < 64; t++) {
                int idx = tid + t * 256;
                int c = idx >> 7, r = idx & 127;
                outb[(size_t)(j0 + c) * NN + (i0 + r)] = stage[r * STAGE_LD + c];
            }
        }
    }
}

// ---------------------------------------------------------------------------
// Kernel D: exact fp32 fixup of near-threshold entries
// ---------------------------------------------------------------------------
__global__ void __launch_bounds__(256)
fixup_kernel(float* __restrict__ out)
{
    unsigned cnt = g_fix_cnt;
    if (cnt > MAXFIX) cnt = MAXFIX;
    for (unsigned t = blockIdx.x * blockDim.x + threadIdx.x; t < cnt;
         t += gridDim.x * blockDim.x) {
        unsigned e = g_fix[t];
        int b = e >> 24, i = (e >> 12) & 0xFFF, j = e & 0xFFF;
        const float4* hi4 = (const float4*)(g_h + ((size_t)b * NN + i) * DOUT);
        const float4* hj4 = (const float4*)(g_h + ((size_t)b * NN + j) * DOUT);
        float dot = 0.f;
#pragma unroll
        for (int k = 0; k < 32; k++) {
            float4 a = hi4[k], c = hj4[k];
            dot += a.x * c.x + a.y * c.y + a.z * c.z + a.w * c.w;
        }
        float denom = fmaxf(g_norm[(size_t)b * NN + i] * g_norm[(size_t)b * NN + j],
                            COS_EPS);
        float v = fabsf(dot) / denom;
        float r = (v > THRESHOLD) ? v : 0.f;
        float* outb = out + (size_t)b * NN * NN;
        outb[(size_t)i * NN + j] = r;
        outb[(size_t)j * NN + i] = r;
    }
}

// ---------------------------------------------------------------------------
extern "C" void kernel_launch(void* const* d_in, const int* in_sizes, int n_in,
                              void* d_out, int out_size)
{
    (void)in_sizes; (void)n_in; (void)out_size;
    const float* z = (const float*)d_in[0];
    const float* W = (const float*)d_in[1];
    float* out = (float*)d_out;

    const int smem1 = (64 * Z_ROWLEN + 64 * DOUT) * sizeof(float);

    static bool attrs_set = false;
    if (!attrs_set) {
        cudaFuncSetAttribute(gemm1_kernel, cudaFuncAttributeMaxDynamicSharedMemorySize, smem1);
        cudaFuncSetAttribute(gram_mma_kernel, cudaFuncAttributeMaxDynamicSharedMemorySize, GRAM_SMEM);
        attrs_set = true;
    }

    reset_kernel<<<1, 1>>>();
    gemm1_kernel<<<BB * NN / 128, 256, smem1>>>(z, W);
    split_kernel<<<BB * NN / 8, 256>>>();
    dim3 grid(NN / 128, NN / 128, BB);
    gram_mma_kernel<<<grid, 256, GRAM_SMEM>>>(out);
    fixup_kernel<<<128, 256>>>(out);
}